// round 1
// baseline (speedup 1.0000x reference)
#include <cuda_runtime.h>

// ---------------------------------------------------------------------------
// NeuralLongTermMemory — fp32 SIMT baseline (Round 1)
//   B=4, S=4096 -> N=16384 tokens, D=1024, H=2048
//   12 dense GEMMs chained on one stream, fused epilogues, deterministic
//   gate reduction (per-block partials, fixed-order tree sum).
// ---------------------------------------------------------------------------

constexpr int NTOK = 16384;
constexpr int DIM  = 1024;
constexpr int HID  = 2048;

constexpr int BM = 128, BN = 128, BK = 16, TPB = 256;

// ---- scratch (static device arrays; no allocation at runtime) --------------
__device__ float g_k  [NTOK * DIM];   // 64 MB
__device__ float g_v  [NTOK * DIM];
__device__ float g_q  [NTOK * DIM];
__device__ float g_z  [NTOK * HID];   // 128 MB (z = k@M1^T; reused for zq)
__device__ float g_h  [NTOK * HID];   // 128 MB (silu(z); reused for hq)
__device__ float g_e  [NTOK * DIM];   // (2/D)(pred - v)
__device__ float g_dz [NTOK * HID];
__device__ float g_ret[NTOK * DIM];
__device__ float g_M1n[HID * DIM];
__device__ float g_M2n[DIM * HID];
__device__ float g_part[3 * 1024];    // per-block sigmoid partial sums
__device__ float g_scal[3];           // alpha, theta, eta

// ---- tile loaders -----------------------------------------------------------
// Load a [128 rows][16 k] tile from row-major src (row stride ld) and
// transpose into dst[k][m] (dst row stride BM).
__device__ __forceinline__ void load_transpose(float* __restrict__ dst,
    const float* __restrict__ src, int ld, int tid)
{
#pragma unroll
  for (int p = 0; p < 2; ++p) {
    int r = (tid >> 2) + p * 64;   // m
    int c = (tid & 3) * 4;         // k
    float4 t = *reinterpret_cast<const float4*>(src + (size_t)r * ld + c);
    dst[(c + 0) * BM + r] = t.x;
    dst[(c + 1) * BM + r] = t.y;
    dst[(c + 2) * BM + r] = t.z;
    dst[(c + 3) * BM + r] = t.w;
  }
}

// Load a [16 k rows][128 cols] tile directly into dst[k][col].
__device__ __forceinline__ void load_direct(float* __restrict__ dst,
    const float* __restrict__ src, int ld, int tid)
{
#pragma unroll
  for (int p = 0; p < 2; ++p) {
    int r = (tid >> 5) + p * 8;    // k
    int c = (tid & 31) * 4;        // col
    float4 t = *reinterpret_cast<const float4*>(src + (size_t)r * ld + c);
    *reinterpret_cast<float4*>(dst + r * BM + c) = t;
  }
}

// ---- GEMM core --------------------------------------------------------------
// Computes a 128x128 output tile: acc[i][j] += sum_k a(m,k)*b(n,k)
//   AMODE 0: a(m,k) = A[m*lda + k]  (row-major M x K)
//   AMODE 1: a(m,k) = A[k*lda + m]  (row-major K x M, i.e. A^T)
//   BMODE 0: b(n,k) = B[n*ldb + k]  (row-major N x K, i.e. B^T operand)
//   BMODE 1: b(n,k) = B[k*ldb + n]  (row-major K x N)
template<int AMODE, int BMODE>
__device__ __forceinline__ void gemm_core(const float* __restrict__ A,
    const float* __restrict__ B, int K, int lda, int ldb, float acc[8][8])
{
  __shared__ __align__(16) float As[BK * BM];
  __shared__ __align__(16) float Bs[BK * BN];
  const int tid   = threadIdx.x;
  const int row_t = (tid >> 4) * 8;
  const int col_t = (tid & 15) * 8;

  for (int kt = 0; kt < K; kt += BK) {
    const float* aSrc = (AMODE == 0)
        ? A + (size_t)blockIdx.y * BM * lda + kt
        : A + (size_t)kt * lda + blockIdx.y * BM;
    const float* bSrc = (BMODE == 0)
        ? B + (size_t)blockIdx.x * BN * ldb + kt
        : B + (size_t)kt * ldb + blockIdx.x * BN;
    if (AMODE == 0) load_transpose(As, aSrc, lda, tid);
    else            load_direct  (As, aSrc, lda, tid);
    if (BMODE == 0) load_transpose(Bs, bSrc, ldb, tid);
    else            load_direct  (Bs, bSrc, ldb, tid);
    __syncthreads();
#pragma unroll
    for (int k = 0; k < BK; ++k) {
      float a[8], b[8];
      *reinterpret_cast<float4*>(&a[0]) = *reinterpret_cast<const float4*>(&As[k * BM + row_t]);
      *reinterpret_cast<float4*>(&a[4]) = *reinterpret_cast<const float4*>(&As[k * BM + row_t + 4]);
      *reinterpret_cast<float4*>(&b[0]) = *reinterpret_cast<const float4*>(&Bs[k * BN + col_t]);
      *reinterpret_cast<float4*>(&b[4]) = *reinterpret_cast<const float4*>(&Bs[k * BN + col_t + 4]);
#pragma unroll
      for (int i = 0; i < 8; ++i)
#pragma unroll
        for (int j = 0; j < 8; ++j)
          acc[i][j] = fmaf(a[i], b[j], acc[i][j]);
    }
    __syncthreads();
  }
}

__device__ __forceinline__ float sigmoidf_(float x) { return 1.f / (1.f + expf(-x)); }

// ---- kernels ----------------------------------------------------------------

// C = A @ B^T (plain store)
__global__ void __launch_bounds__(TPB)
k_gemm_nt(const float* __restrict__ A, const float* __restrict__ B,
          float* __restrict__ C, int K, int lda, int ldb, int ldc)
{
  float acc[8][8] = {};
  gemm_core<0, 0>(A, B, K, lda, ldb, acc);
  int r0 = blockIdx.y * BM + (threadIdx.x >> 4) * 8;
  int c0 = blockIdx.x * BN + (threadIdx.x & 15) * 8;
#pragma unroll
  for (int i = 0; i < 8; ++i) {
    float4* p = reinterpret_cast<float4*>(C + (size_t)(r0 + i) * ldc + c0);
    p[0] = make_float4(acc[i][0], acc[i][1], acc[i][2], acc[i][3]);
    p[1] = make_float4(acc[i][4], acc[i][5], acc[i][6], acc[i][7]);
  }
}

// gate: per-block sum of sigmoid(A@B^T + bias) -> partial[block]
__global__ void __launch_bounds__(TPB)
k_gemm_gate(const float* __restrict__ A, const float* __restrict__ B,
            const float* __restrict__ bias, float* __restrict__ partial,
            int K, int lda, int ldb)
{
  float acc[8][8] = {};
  gemm_core<0, 0>(A, B, K, lda, ldb, acc);
  int c0 = blockIdx.x * BN + (threadIdx.x & 15) * 8;
  float s = 0.f;
#pragma unroll
  for (int i = 0; i < 8; ++i)
#pragma unroll
    for (int j = 0; j < 8; ++j)
      s += sigmoidf_(acc[i][j] + bias[c0 + j]);
  __shared__ float red[TPB];
  red[threadIdx.x] = s;
  __syncthreads();
  for (int off = TPB / 2; off > 0; off >>= 1) {
    if (threadIdx.x < off) red[threadIdx.x] += red[threadIdx.x + off];
    __syncthreads();
  }
  if (threadIdx.x == 0)
    partial[blockIdx.y * gridDim.x + blockIdx.x] = red[0];
}

// deterministic gate finalize: scal[g] = mean over N*D of sigmoid values
__global__ void __launch_bounds__(TPB)
k_finalize()
{
  __shared__ float red[TPB];
  for (int g = 0; g < 3; ++g) {
    float s = 0.f;
    for (int i = threadIdx.x; i < 1024; i += TPB) s += g_part[g * 1024 + i];
    red[threadIdx.x] = s;
    __syncthreads();
    for (int off = TPB / 2; off > 0; off >>= 1) {
      if (threadIdx.x < off) red[threadIdx.x] += red[threadIdx.x + off];
      __syncthreads();
    }
    if (threadIdx.x == 0)
      g_scal[g] = red[0] * (1.f / ((float)NTOK * (float)DIM));
    __syncthreads();
  }
}

// Z = A @ B^T ; H = silu(Z)
__global__ void __launch_bounds__(TPB)
k_gemm_silu(const float* __restrict__ A, const float* __restrict__ B,
            float* __restrict__ Z, float* __restrict__ Hs,
            int K, int lda, int ldb, int ldc)
{
  float acc[8][8] = {};
  gemm_core<0, 0>(A, B, K, lda, ldb, acc);
  int r0 = blockIdx.y * BM + (threadIdx.x >> 4) * 8;
  int c0 = blockIdx.x * BN + (threadIdx.x & 15) * 8;
#pragma unroll
  for (int i = 0; i < 8; ++i)
#pragma unroll
    for (int j = 0; j < 8; ++j) {
      size_t idx = (size_t)(r0 + i) * ldc + c0 + j;
      float zv = acc[i][j];
      Z[idx]  = zv;
      Hs[idx] = zv * sigmoidf_(zv);
    }
}

// E = scale * (A @ B^T - V)
__global__ void __launch_bounds__(TPB)
k_gemm_err(const float* __restrict__ A, const float* __restrict__ B,
           const float* __restrict__ V, float* __restrict__ E,
           int K, int lda, int ldb, int ldc, float scale)
{
  float acc[8][8] = {};
  gemm_core<0, 0>(A, B, K, lda, ldb, acc);
  int r0 = blockIdx.y * BM + (threadIdx.x >> 4) * 8;
  int c0 = blockIdx.x * BN + (threadIdx.x & 15) * 8;
#pragma unroll
  for (int i = 0; i < 8; ++i)
#pragma unroll
    for (int j = 0; j < 8; ++j) {
      size_t idx = (size_t)(r0 + i) * ldc + c0 + j;
      E[idx] = scale * (acc[i][j] - V[idx]);
    }
}

// DZ = (A @ B) * silu'(Z)      (NN: B row-major K x N)
__global__ void __launch_bounds__(TPB)
k_gemm_dz(const float* __restrict__ A, const float* __restrict__ B,
          const float* __restrict__ Z, float* __restrict__ DZ,
          int K, int lda, int ldb, int ldc)
{
  float acc[8][8] = {};
  gemm_core<0, 1>(A, B, K, lda, ldb, acc);
  int r0 = blockIdx.y * BM + (threadIdx.x >> 4) * 8;
  int c0 = blockIdx.x * BN + (threadIdx.x & 15) * 8;
#pragma unroll
  for (int i = 0; i < 8; ++i)
#pragma unroll
    for (int j = 0; j < 8; ++j) {
      size_t idx = (size_t)(r0 + i) * ldc + c0 + j;
      float zv = Z[idx];
      float sg = sigmoidf_(zv);
      DZ[idx] = acc[i][j] * (sg * (1.f + zv * (1.f - sg)));
    }
}

// G = A^T @ B ; Mnew = (1-alpha)*Mold + eta*Sold - theta*G   (TN)
__global__ void __launch_bounds__(TPB)
k_gemm_upd(const float* __restrict__ A, const float* __restrict__ B,
           const float* __restrict__ Mold, const float* __restrict__ Sold,
           float* __restrict__ Mnew, int K, int lda, int ldb, int ldc)
{
  float acc[8][8] = {};
  gemm_core<1, 1>(A, B, K, lda, ldb, acc);
  float al = g_scal[0], th = g_scal[1], et = g_scal[2];
  int r0 = blockIdx.y * BM + (threadIdx.x >> 4) * 8;
  int c0 = blockIdx.x * BN + (threadIdx.x & 15) * 8;
#pragma unroll
  for (int i = 0; i < 8; ++i)
#pragma unroll
    for (int j = 0; j < 8; ++j) {
      size_t idx = (size_t)(r0 + i) * ldc + c0 + j;
      Mnew[idx] = (1.f - al) * Mold[idx] + et * Sold[idx] - th * acc[i][j];
    }
}

// ---- launch ------------------------------------------------------------------
extern "C" void kernel_launch(void* const* d_in, const int* in_sizes, int n_in,
                              void* d_out, int out_size)
{
  (void)in_sizes; (void)n_in; (void)out_size;
  const float* x    = (const float*)d_in[0];
  const float* Wk   = (const float*)d_in[1];
  const float* Wv   = (const float*)d_in[2];
  const float* Wq   = (const float*)d_in[3];
  const float* Wout = (const float*)d_in[4];
  const float* Wgd  = (const float*)d_in[5];
  const float* bgd  = (const float*)d_in[6];
  const float* Wgl  = (const float*)d_in[7];
  const float* bgl  = (const float*)d_in[8];
  const float* Wgm  = (const float*)d_in[9];
  const float* bgm  = (const float*)d_in[10];
  const float* M1   = (const float*)d_in[11];
  const float* M2   = (const float*)d_in[12];
  const float* S1   = (const float*)d_in[13];
  const float* S2   = (const float*)d_in[14];

  float *k_, *v_, *q_, *z_, *h_, *e_, *dz_, *ret_, *M1n_, *M2n_, *part_;
  cudaGetSymbolAddress((void**)&k_,   g_k);
  cudaGetSymbolAddress((void**)&v_,   g_v);
  cudaGetSymbolAddress((void**)&q_,   g_q);
  cudaGetSymbolAddress((void**)&z_,   g_z);
  cudaGetSymbolAddress((void**)&h_,   g_h);
  cudaGetSymbolAddress((void**)&e_,   g_e);
  cudaGetSymbolAddress((void**)&dz_,  g_dz);
  cudaGetSymbolAddress((void**)&ret_, g_ret);
  cudaGetSymbolAddress((void**)&M1n_, g_M1n);
  cudaGetSymbolAddress((void**)&M2n_, g_M2n);
  cudaGetSymbolAddress((void**)&part_, g_part);

  dim3 t(TPB);
  dim3 gP (DIM / BN, NTOK / BM);   // (8, 128)  N x D outputs
  dim3 gH (HID / BN, NTOK / BM);   // (16, 128) N x H outputs
  dim3 gU1(DIM / BN, HID  / BM);   // (8, 16)   H x D (M1 update)
  dim3 gU2(HID / BN, DIM  / BM);   // (16, 8)   D x H (M2 update)

  // projections: N x D = x @ W^T
  k_gemm_nt<<<gP, t>>>(x, Wk, k_, DIM, DIM, DIM, DIM);
  k_gemm_nt<<<gP, t>>>(x, Wv, v_, DIM, DIM, DIM, DIM);
  k_gemm_nt<<<gP, t>>>(x, Wq, q_, DIM, DIM, DIM, DIM);

  // gates: mean(sigmoid(x @ Wg^T + b))
  k_gemm_gate<<<gP, t>>>(x, Wgd, bgd, part_ + 0 * 1024, DIM, DIM, DIM);
  k_gemm_gate<<<gP, t>>>(x, Wgl, bgl, part_ + 1 * 1024, DIM, DIM, DIM);
  k_gemm_gate<<<gP, t>>>(x, Wgm, bgm, part_ + 2 * 1024, DIM, DIM, DIM);
  k_finalize<<<1, t>>>();

  // memory forward on k: z = k @ M1^T (N x H), h = silu(z)
  k_gemm_silu<<<gH, t>>>(k_, M1, z_, h_, DIM, DIM, DIM, HID);

  // e = (2/D) * (h @ M2^T - v)   (N x D)
  k_gemm_err<<<gP, t>>>(h_, M2, v_, e_, HID, HID, HID, DIM, 2.f / (float)DIM);

  // dz = (e @ M2) * silu'(z)     (N x H, NN)
  k_gemm_dz<<<gH, t>>>(e_, M2, z_, dz_, DIM, DIM, HID, HID);

  // M1n = (1-alpha)M1 + eta*S1 - theta*(dz^T @ k)   (H x D, K = N)
  k_gemm_upd<<<gU1, t>>>(dz_, k_, M1, S1, M1n_, NTOK, HID, DIM, DIM);
  // M2n = (1-alpha)M2 + eta*S2 - theta*(e^T @ h)    (D x H, K = N)
  k_gemm_upd<<<gU2, t>>>(e_, h_, M2, S2, M2n_, NTOK, DIM, HID, HID);

  // retrieval: hq = silu(q @ M1n^T); ret = hq @ M2n^T; out = ret @ Wout^T
  k_gemm_silu<<<gH, t>>>(q_, M1n_, z_, h_, DIM, DIM, DIM, HID);
  k_gemm_nt<<<gP, t>>>(h_, M2n_, ret_, HID, HID, HID, DIM);
  k_gemm_nt<<<gP, t>>>(ret_, Wout, (float*)d_out, DIM, DIM, DIM, DIM);
}